// round 1
// baseline (speedup 1.0000x reference)
#include <cuda_runtime.h>

#define B_  2
#define N_  30000
#define C_  32
#define H_  96
#define W_  96
#define D_  96
#define K_  27
#define V_  8
#define TPB 128
#define CS_ (H_*W_*D_)     /* channel stride  */
#define BS_ (C_*CS_)       /* batch stride    */
#define IK_ (C_*K_)        /* 864 */

__device__ float g_wT[IK_ * C_];   // wT[(i*27+k)*32 + o] = conv_w[o][i][0][k]

__global__ void wt_transpose_kernel(const float* __restrict__ w)
{
    int idx = blockIdx.x * blockDim.x + threadIdx.x;
    if (idx < IK_ * C_) {
        int o = idx % C_;
        int t = idx / C_;          // t = i*27 + k
        int i = t / K_;
        int k = t % K_;
        g_wT[idx] = w[(o * C_ + i) * K_ + k];
    }
}

__global__ __launch_bounds__(TPB)
void nfs_kernel(const float* __restrict__ vox,
                const float* __restrict__ verts,
                const float* __restrict__ bias,
                float* __restrict__ out)
{
    // [9]-padded inner dim: 9 coprime to 32 -> conflict-free LDS in phase 1
    __shared__ float s_w[V_][K_][9];
    __shared__ int   s_c[V_][K_][9];
    __shared__ float s_feat[V_][IK_];
    __shared__ float s_part[4][V_][C_];

    const int tid = threadIdx.x;
    const int gv0 = blockIdx.x * V_;

    // ---- Phase 0: per-sample corner indices + trilinear weights (V*27 = 216 tasks)
    for (int t = tid; t < V_ * K_; t += TPB) {
        int v = t / K_, k = t % K_;
        int gv = gv0 + v;
        float x = verts[gv * 3 + 0];
        float y = verts[gv * 3 + 1];
        float z = verts[gv * 3 + 2];

        int p = k / 9 - 1;          // offs component 0 -> x (D axis)
        int q = (k / 3) % 3 - 1;    // component 1 -> y (W axis)
        int r = k % 3 - 1;          // component 2 -> z (H axis)

        const float sxc = (float)(2.0 / (D_ - 1));
        const float syc = (float)(2.0 / (W_ - 1));
        const float szc = (float)(2.0 / (H_ - 1));

        float gx = x + (float)p * sxc;
        float gy = y + (float)q * syc;
        float gz = z + (float)r * szc;

        float ix = (gx + 1.0f) * 0.5f * (float)(D_ - 1);
        float iy = (gy + 1.0f) * 0.5f * (float)(W_ - 1);
        float iz = (gz + 1.0f) * 0.5f * (float)(H_ - 1);
        ix = fminf(fmaxf(ix, 0.0f), (float)(D_ - 1));
        iy = fminf(fmaxf(iy, 0.0f), (float)(W_ - 1));
        iz = fminf(fmaxf(iz, 0.0f), (float)(H_ - 1));

        int x0 = (int)floorf(ix), y0 = (int)floorf(iy), z0 = (int)floorf(iz);
        int x1 = min(x0 + 1, D_ - 1);
        int y1 = min(y0 + 1, W_ - 1);
        int z1 = min(z0 + 1, H_ - 1);
        float fx = ix - (float)x0, fy = iy - (float)y0, fz = iz - (float)z0;
        float gxw = 1.0f - fx, gyw = 1.0f - fy, gzw = 1.0f - fz;

        s_c[v][k][0] = (z0 * W_ + y0) * D_ + x0;  s_w[v][k][0] = gzw * gyw * gxw;
        s_c[v][k][1] = (z0 * W_ + y0) * D_ + x1;  s_w[v][k][1] = gzw * gyw * fx;
        s_c[v][k][2] = (z0 * W_ + y1) * D_ + x0;  s_w[v][k][2] = gzw * fy  * gxw;
        s_c[v][k][3] = (z0 * W_ + y1) * D_ + x1;  s_w[v][k][3] = gzw * fy  * fx;
        s_c[v][k][4] = (z1 * W_ + y0) * D_ + x0;  s_w[v][k][4] = fz  * gyw * gxw;
        s_c[v][k][5] = (z1 * W_ + y0) * D_ + x1;  s_w[v][k][5] = fz  * gyw * fx;
        s_c[v][k][6] = (z1 * W_ + y1) * D_ + x0;  s_w[v][k][6] = fz  * fy  * gxw;
        s_c[v][k][7] = (z1 * W_ + y1) * D_ + x1;  s_w[v][k][7] = fz  * fy  * fx;
    }
    __syncthreads();

    // ---- Phase 1: gather + trilinear blend (V*864 = 6912 tasks)
    for (int t = tid; t < V_ * IK_; t += TPB) {
        int v  = t / IK_;
        int ik = t % IK_;
        int i  = ik / K_;
        int k  = ik % K_;
        int gv = gv0 + v;
        int b  = gv / N_;
        const float* base = vox + (size_t)b * BS_ + (size_t)i * CS_;
        float acc = 0.0f;
        #pragma unroll
        for (int j = 0; j < 8; ++j)
            acc = fmaf(__ldg(base + s_c[v][k][j]), s_w[v][k][j], acc);
        s_feat[v][ik] = acc;
    }
    __syncthreads();

    // ---- Phase 2: out[v][o] = sum_ik feat[v][ik] * wT[ik][o]
    {
        const int g    = tid >> 5;      // 4 groups
        const int lane = tid & 31;      // o
        const int TPG  = IK_ / 4;       // 216 ik-terms per group
        float acc[V_];
        #pragma unroll
        for (int v = 0; v < V_; ++v) acc[v] = 0.0f;

        const int t0 = g * TPG;
        for (int t = t0; t < t0 + TPG; ++t) {
            float wv = g_wT[t * C_ + lane];   // coalesced 128B per iteration
            #pragma unroll
            for (int v = 0; v < V_; ++v)
                acc[v] = fmaf(s_feat[v][t], wv, acc[v]);
        }
        #pragma unroll
        for (int v = 0; v < V_; ++v) s_part[g][v][lane] = acc[v];
    }
    __syncthreads();

    // ---- Final reduce across the 4 groups + bias + store (256 outputs, 2/thread)
    for (int t = tid; t < V_ * C_; t += TPB) {
        int v = t / C_, o = t % C_;
        float r = s_part[0][v][o] + s_part[1][v][o] +
                  s_part[2][v][o] + s_part[3][v][o] + __ldg(bias + o);
        int gv = gv0 + v;
        out[(size_t)gv * C_ + o] = r;
    }
}

extern "C" void kernel_launch(void* const* d_in, const int* in_sizes, int n_in,
                              void* d_out, int out_size)
{
    const float* vox   = (const float*)d_in[0];  // (2,32,96,96,96)
    const float* verts = (const float*)d_in[1];  // (2,30000,3)
    const float* cw    = (const float*)d_in[2];  // (32,32,1,27)
    const float* cb    = (const float*)d_in[3];  // (32,)
    float* out = (float*)d_out;                  // (2,30000,32)

    (void)in_sizes; (void)n_in; (void)out_size;

    wt_transpose_kernel<<<(IK_ * C_ + 255) / 256, 256>>>(cw);

    const int nblocks = (B_ * N_) / V_;          // 7500
    nfs_kernel<<<nblocks, TPB>>>(vox, verts, cb, out);
}

// round 2
// speedup vs baseline: 2.0071x; 2.0071x over previous
#include <cuda_runtime.h>

#define B_  2
#define N_  30000
#define C_  32
#define H_  96
#define W_  96
#define D_  96
#define K_  27
#define V_  8
#define TPB 256
#define CS_ (H_*W_*D_)     /* channel stride  */
#define BS_ (C_*CS_)       /* batch stride    */
#define IK_ (C_*K_)        /* 864 */
#define GP  67             /* smem window pitch: gcd(67-64.., (3i)%32 conflict-free */

__device__ float g_wT[IK_ * C_];   // wT[(i*27+k)*32 + o] = conv_w[o][i][0][k]

__global__ void wt_transpose_kernel(const float* __restrict__ w)
{
    int idx = blockIdx.x * blockDim.x + threadIdx.x;
    if (idx < IK_ * C_) {
        int o = idx % C_;
        int t = idx / C_;          // t = i*27 + k
        int i = t / K_;
        int k = t % K_;
        g_wT[idx] = w[(o * C_ + i) * K_ + k];
    }
}

__global__ __launch_bounds__(TPB, 4)
void nfs_kernel(const float* __restrict__ vox,
                const float* __restrict__ verts,
                const float* __restrict__ bias,
                float* __restrict__ out)
{
    __shared__ float s_g[C_][GP];          // 4x4x4 window per channel (j = sz*16+sy*4+sx)
    __shared__ float s_feat[V_][IK_];
    __shared__ float s_part[8][V_][C_];
    __shared__ int   s_sl0[V_][3][3];      // [v][axis][p] corner0 slot (0..3)
    __shared__ int   s_sl1[V_][3][3];      // corner1 slot
    __shared__ float s_fr [V_][3][3];      // fraction
    __shared__ int   s_cx[V_][4];          // absolute x coord
    __shared__ int   s_cy[V_][4];          // y coord * D
    __shared__ int   s_cz[V_][4];          // z coord * W * D

    const int tid = threadIdx.x;
    const int gv0 = blockIdx.x * V_;
    const int b   = gv0 / N_;              // block never straddles a batch (N_ % V_ == 0)

    // ---- Phase A: per-vertex per-axis sample math (exact reference order) ----
    if (tid < V_ * 3) {
        const int v = tid / 3, a = tid % 3;    // a: 0->x(D), 1->y(W), 2->z(H); dims all 96
        const float coord = verts[(gv0 + v) * 3 + a];
        const float sc = (float)(2.0 / (D_ - 1));
        int i0[3], i1[3];
        float fr[3];
        #pragma unroll
        for (int p = 0; p < 3; ++p) {
            float gp = coord + (float)(p - 1) * sc;
            float ip = (gp + 1.0f) * 0.5f * (float)(D_ - 1);
            ip = fminf(fmaxf(ip, 0.0f), (float)(D_ - 1));
            i0[p] = (int)floorf(ip);
            i1[p] = min(i0[p] + 1, D_ - 1);
            fr[p] = ip - (float)i0[p];
        }
        const int wb = i0[1] - 1;          // window base
        #pragma unroll
        for (int p = 0; p < 3; ++p) {
            s_sl0[v][a][p] = min(max(i0[p] - wb, 0), 3);
            s_sl1[v][a][p] = min(max(i1[p] - wb, 0), 3);
            s_fr [v][a][p] = fr[p];
        }
        #pragma unroll
        for (int j = 0; j < 4; ++j) {
            int cj = min(max(wb + j, 0), D_ - 1);
            if      (a == 0) s_cx[v][j] = cj;
            else if (a == 1) s_cy[v][j] = cj * D_;
            else             s_cz[v][j] = cj * (W_ * D_);
        }
    }
    __syncthreads();

    const float* base = vox + (size_t)b * BS_;

    for (int v = 0; v < V_; ++v) {
        // ---- Stage 1: gather 32ch x 64-voxel window into smem ----
        {
            const int j  = tid & 63;
            const int sx = j & 3, sy = (j >> 2) & 3, sz = j >> 4;
            const int ro = s_cz[v][sz] + s_cy[v][sy] + s_cx[v][sx];
            #pragma unroll
            for (int c = tid >> 6; c < C_; c += TPB / 64)
                s_g[c][j] = __ldg(base + (size_t)c * CS_ + ro);
        }
        __syncthreads();

        // ---- Stage 2: 864 trilinear blends from smem window ----
        for (int t = tid; t < IK_; t += TPB) {
            const int i = t & 31;          // channel (varies across lanes)
            const int k = t >> 5;          // sample  (uniform per warp)
            const int p = k / 9, q = (k / 3) % 3, r = k % 3;

            const int sx0 = s_sl0[v][0][p], sx1 = s_sl1[v][0][p];
            const int sy0 = s_sl0[v][1][q] * 4, sy1 = s_sl1[v][1][q] * 4;
            const int sz0 = s_sl0[v][2][r] * 16, sz1 = s_sl1[v][2][r] * 16;
            const float fx = s_fr[v][0][p], fy = s_fr[v][1][q], fz = s_fr[v][2][r];
            const float gx = 1.0f - fx, gy = 1.0f - fy, gz = 1.0f - fz;

            const float* gi = s_g[i];
            float acc;
            acc  = gi[sz0 + sy0 + sx0] * (gz * gy * gx);
            acc += gi[sz0 + sy0 + sx1] * (gz * gy * fx);
            acc += gi[sz0 + sy1 + sx0] * (gz * fy * gx);
            acc += gi[sz0 + sy1 + sx1] * (gz * fy * fx);
            acc += gi[sz1 + sy0 + sx0] * (fz * gy * gx);
            acc += gi[sz1 + sy0 + sx1] * (fz * gy * fx);
            acc += gi[sz1 + sy1 + sx0] * (fz * fy * gx);
            acc += gi[sz1 + sy1 + sx1] * (fz * fy * fx);
            s_feat[v][i * K_ + k] = acc;
        }
        __syncthreads();
    }

    // ---- GEMM: out[v][o] = sum_ik feat[v][ik] * wT[ik][o] ----
    {
        const int g    = tid >> 5;         // 8 groups
        const int lane = tid & 31;         // o
        const int TPG  = IK_ / 8;          // 108
        float acc[V_];
        #pragma unroll
        for (int v = 0; v < V_; ++v) acc[v] = 0.0f;

        const int t0 = g * TPG;
        for (int t = t0; t < t0 + TPG; ++t) {
            const float wv = g_wT[t * C_ + lane];
            #pragma unroll
            for (int v = 0; v < V_; ++v)
                acc[v] = fmaf(s_feat[v][t], wv, acc[v]);
        }
        #pragma unroll
        for (int v = 0; v < V_; ++v) s_part[g][v][lane] = acc[v];
    }
    __syncthreads();

    // ---- Final reduce + bias + store ----
    if (tid < V_ * C_) {
        const int v = tid / C_, o = tid % C_;
        float r = __ldg(bias + o);
        #pragma unroll
        for (int g = 0; g < 8; ++g) r += s_part[g][v][o];
        out[(size_t)(gv0 + v) * C_ + o] = r;
    }
}

extern "C" void kernel_launch(void* const* d_in, const int* in_sizes, int n_in,
                              void* d_out, int out_size)
{
    const float* vox   = (const float*)d_in[0];  // (2,32,96,96,96)
    const float* verts = (const float*)d_in[1];  // (2,30000,3)
    const float* cw    = (const float*)d_in[2];  // (32,32,1,27)
    const float* cb    = (const float*)d_in[3];  // (32,)
    float* out = (float*)d_out;                  // (2,30000,32)

    (void)in_sizes; (void)n_in; (void)out_size;

    wt_transpose_kernel<<<(IK_ * C_ + 255) / 256, 256>>>(cw);

    const int nblocks = (B_ * N_) / V_;          // 7500
    nfs_kernel<<<nblocks, TPB>>>(vox, verts, cb, out);
}